// round 11
// baseline (speedup 1.0000x reference)
#include <cuda_runtime.h>
#include <cuda_bf16.h>
#include <cstdint>
#include <math.h>

#define LSEQ 512
#define CP   128

// ======================= device globals (no allocation) =======================
__device__ float g_A[LSEQ * CP];            // b1 + p_i[i] . W1[:,0:64]
__device__ float g_B[LSEQ * CP];            // p_i[j] . W1[:,64:128]
__device__ float g_C[1023 * CP];            // relpos path . W1[:,128:192]

__device__ __forceinline__ float rtf32(float x) {
    float r;
    asm("cvt.rna.tf32.f32 %0, %1;" : "=f"(r) : "f"(x));
    return r;
}

// m16n8k8 tf32 mma: acc (4 f32), A-frag (uint4), B-frag (2 u32)
#define MMA8(c, a, b0, b1)                                                      \
    asm volatile("mma.sync.aligned.m16n8k8.row.col.f32.tf32.tf32.f32 "          \
                 "{%0,%1,%2,%3}, {%4,%5,%6,%7}, {%8,%9}, {%0,%1,%2,%3};"        \
                 : "+f"((c)[0]), "+f"((c)[1]), "+f"((c)[2]), "+f"((c)[3])       \
                 : "r"((a).x), "r"((a).y), "r"((a).z), "r"((a).w),              \
                   "r"(b0), "r"(b1))

// ======================= merged prep kernel (unchanged from R9) =======================
__global__ void k_prep(const float* __restrict__ s, const float* __restrict__ Wsp,
                       const float* __restrict__ bsp, const float* __restrict__ Wrp,
                       const float* __restrict__ brp, const float* __restrict__ W1,
                       const float* __restrict__ b1) {
    extern __shared__ float sm1[];
    const int tid = threadIdx.x;   // 256
    const int blk = blockIdx.x;
    if (blk < 64) {
        float* sWspT = sm1;                        // [d=256][f=64] pad 65
        float* sW1T  = sm1 + 256 * 65;             // [c=128][p=128] pad 129
        float* srow  = sW1T + 128 * 129;           // [8][256]
        float* prow  = srow + 8 * 256;             // [8][64]
        const int ii0 = blk * 8;

        #pragma unroll 8
        for (int x = tid; x < 64 * 256; x += 256) {
            int f = x >> 8, d = x & 255;
            sWspT[d * 65 + f] = Wsp[x];
        }
        #pragma unroll 8
        for (int x = tid; x < 128 * 128; x += 256) {
            int p = x >> 7, c = x & 127;
            sW1T[c * 129 + p] = W1[p * 256 + c];
        }
        #pragma unroll
        for (int x = tid; x < 8 * 256; x += 256)
            srow[x] = s[ii0 * 256 + x];
        __syncthreads();

        {
            const int f = tid & 63, il = tid >> 6;
            #pragma unroll
            for (int rep = 0; rep < 2; rep++) {
                const int i_loc = rep * 4 + il;
                float acc0 = bsp[f], acc1 = 0.0f;
                const float* sr = srow + i_loc * 256;
                #pragma unroll 8
                for (int d = 0; d < 256; d += 2) {
                    acc0 = fmaf(sr[d], sWspT[d * 65 + f], acc0);
                    acc1 = fmaf(sr[d + 1], sWspT[(d + 1) * 65 + f], acc1);
                }
                prow[i_loc * 64 + f] = acc0 + acc1;
            }
        }
        __syncthreads();
        {
            const int p = tid & 127, il = tid >> 7;
            #pragma unroll
            for (int rep = 0; rep < 4; rep++) {
                const int i_loc = rep * 2 + il;
                float a = b1[p], b = 0.0f;
                const float* pr = prow + i_loc * 64;
                #pragma unroll
                for (int fx = 0; fx < 64; fx++) {
                    float pv = pr[fx];
                    a = fmaf(pv, sW1T[fx * 129 + p], a);
                    b = fmaf(pv, sW1T[(64 + fx) * 129 + p], b);
                }
                g_A[(ii0 + i_loc) * CP + p] = a;
                g_B[(ii0 + i_loc) * CP + p] = b;
            }
        }
    } else {
        float* sWrpT  = sm1;                   // [g=64][f=64] pad 65
        float* sW1cT  = sm1 + 64 * 65;         // [g=64][p=128] pad 129
        float* semb   = sW1cT + 64 * 129;      // [4][64]
        float* srp    = semb + 4 * 64;         // [4][64]
        #pragma unroll 8
        for (int x = tid; x < 64 * 64; x += 256) {
            int f = x >> 6, g = x & 63;
            sWrpT[g * 65 + f] = Wrp[x];
        }
        #pragma unroll 8
        for (int x = tid; x < 128 * 64; x += 256) {
            int p = x >> 6, g = x & 63;
            sW1cT[g * 129 + p] = W1[p * 256 + 128 + g];
        }
        __syncthreads();
        const int d_base = (blk - 64) * 64;
        const int grp = tid >> 6, t2 = tid & 63;
        for (int it = 0; it < 16; it++) {
            const int d = d_base + it * 4 + grp;
            if (t2 < 32 && d < 1023) {
                const float L2 = 11.005624549193878f;   // log2(2056)
                float x = (float)(d - 511) * exp2f(-(float)t2 * (L2 / 32.0f));
                float sv, cv;
                sincospif(x, &sv, &cv);
                semb[grp * 64 + t2] = sv;
                semb[grp * 64 + 32 + t2] = cv;
            }
            __syncthreads();
            if (d < 1023) {
                float acc = brp[t2];
                const float* em = semb + grp * 64;
                #pragma unroll
                for (int g = 0; g < 64; g++) acc = fmaf(em[g], sWrpT[g * 65 + t2], acc);
                srp[grp * 64 + t2] = acc;
            }
            __syncthreads();
            {
                const int p = tid & 127;
                #pragma unroll
                for (int dd = 0; dd < 2; dd++) {
                    const int dl = (tid >> 7) + 2 * dd;
                    const int dg = d_base + it * 4 + dl;
                    if (dg < 1023) {
                        float acc = 0.0f;
                        const float* rpp = srp + dl * 64;
                        #pragma unroll
                        for (int g = 0; g < 64; g++) acc = fmaf(rpp[g], sW1cT[g * 129 + p], acc);
                        g_C[dg * CP + p] = acc;
                    }
                }
            }
            __syncthreads();
        }
    }
}

// ======================= main kernel: raw m16n8k8 tf32, permuted operands =======================
// smem (floats):
//   sW1p [0, 8192)      : W1s B-frags, blocks (kbp 0..3)x(nb 0..15), 128 floats each
//   sW2p [8192, 24576)  : W2  B-frags, blocks (kbp 0..7)x(nb 0..15)
//   sEp  [24576, 32768) : E   A-frags, blocks (mb 0..7)x(kb 0..7)
//   sHp  [32768, 49152) : H   A-frags, blocks (mb 0..7)x(kb 0..15)
//   sArow[49152, 49280) : g_A row for current i
#define OFF_W1P 0
#define OFF_W2P 8192
#define OFF_EP  24576
#define OFF_HP  32768
#define OFF_AR  49152
#define SMEM_TOTAL (49280 * 4)

__global__ __launch_bounds__(256, 1)
void k_main(const float* __restrict__ t, const float* __restrict__ sct,
            const float* __restrict__ pre, const float* __restrict__ W1g,
            const float* __restrict__ W2g, const float* __restrict__ b2v,
            float* __restrict__ out) {
    extern __shared__ float smf[];
    float* sW1p = smf + OFF_W1P;
    float* sW2p = smf + OFF_W2P;
    float* sEp  = smf + OFF_EP;
    float* sHp  = smf + OFF_HP;
    float* sArow = smf + OFF_AR;

    const int tid = threadIdx.x;
    const int wid = tid >> 5;
    const int lane = tid & 31;
    const int wm = wid >> 1;          // 0..3: rows [wm*32, +32)
    const int wn = wid & 1;           // 0..1: cols [wn*64, +64)
    const int g  = lane >> 2;         // acc row-in-8
    const int tg = lane & 3;          // acc col-pair

    // ---- stage permuted tf32 weights once ----
    #pragma unroll 8
    for (int x = tid; x < 128 * 64; x += 256) {
        int n = x >> 6, k = x & 63;                  // k fast -> coalesced LDG
        float v = rtf32(W1g[n * 256 + 192 + k]);
        int kb = k >> 3, nb = n >> 3;
        int idx = ((kb >> 1) * 16 + nb) * 128 + ((n & 7) * 4 + (k & 3)) * 4
                + (kb & 1) * 2 + ((k >> 2) & 1);
        sW1p[idx] = v;
    }
    #pragma unroll 8
    for (int x = tid; x < 128 * 128; x += 256) {
        int q = x >> 7, p = x & 127;                 // p fast -> coalesced LDG
        float v = rtf32(W2g[x]);
        int kb = p >> 3, nb = q >> 3;
        int idx = ((kb >> 1) * 16 + nb) * 128 + ((q & 7) * 4 + (p & 3)) * 4
                + (kb & 1) * 2 + ((p >> 2) & 1);
        sW2p[idx] = v;
    }
    // per-thread b2 cols (constant across tiles)
    float2 b2r[8];
    #pragma unroll
    for (int nbl = 0; nbl < 8; nbl++)
        b2r[nbl] = *(const float2*)(b2v + wn * 64 + nbl * 8 + 2 * tg);
    __syncthreads();

    for (int tile = blockIdx.x; tile < 2048; tile += gridDim.x) {
        const int i = tile >> 2;
        const int j0 = (tile & 3) << 7;

        // ---- phase0: build E (A-frag permuted) + stage A row ----
        {
            const int half = tid >> 7, m = tid & 127, j = j0 + m;
            const int r16 = m & 15;
            const int ebase = ((m >> 4) * 8) * 128 + (r16 & 7) * 16 + ((r16 >> 3) & 1);
            const float* P = half ? sct : t;
            float dx = P[3 * i + 0] - P[3 * j + 0];
            float dy = P[3 * i + 1] - P[3 * j + 1];
            float dz = P[3 * i + 2] - P[3 * j + 2];
            float dist = sqrtf(dx * dx + dy * dy + dz * dz);
            const float inv_sig = 22.0f / 20.0f, step = 20.0f / 21.0f;
            #pragma unroll
            for (int kk = 0; kk < 22; kk++) {
                float r = (dist - kk * step) * inv_sig;
                int k = half * 22 + kk;
                int idx = ebase + (k >> 3) * 128 + (k & 3) * 4 + (((k >> 2) & 1) << 1);
                sEp[idx] = rtf32(__expf(-r * r));
            }
            const float2* pp = (const float2*)(pre + ((size_t)(i * LSEQ + j)) * 20 + half * 10);
            #pragma unroll
            for (int c = 0; c < 5; c++) {
                float2 v = pp[c];
                int k0 = 44 + half * 10 + 2 * c;
                int k1 = k0 + 1;
                int i0x = ebase + (k0 >> 3) * 128 + (k0 & 3) * 4 + (((k0 >> 2) & 1) << 1);
                int i1x = ebase + (k1 >> 3) * 128 + (k1 & 3) * 4 + (((k1 >> 2) & 1) << 1);
                sEp[i0x] = rtf32(v.x);
                sEp[i1x] = rtf32(v.y);
            }
            if (tid < 128) sArow[tid] = g_A[i * CP + tid];
        }
        __syncthreads();

        // ---- GEMM1: D1 = E @ W1s (K=64) ----
        float acc[2][8][4];
        #pragma unroll
        for (int mb = 0; mb < 2; mb++)
            #pragma unroll
            for (int nbl = 0; nbl < 8; nbl++)
                #pragma unroll
                for (int u = 0; u < 4; u++) acc[mb][nbl][u] = 0.0f;

        #pragma unroll
        for (int kbp = 0; kbp < 4; kbp++) {
            uint4 bb[8];
            #pragma unroll
            for (int nbl = 0; nbl < 8; nbl++)
                bb[nbl] = *(const uint4*)(sW1p + (kbp * 16 + wn * 8 + nbl) * 128 + lane * 4);
            #pragma unroll
            for (int mb = 0; mb < 2; mb++) {
                const int mbG = wm * 2 + mb;
                uint4 a0 = *(const uint4*)(sEp + (mbG * 8 + 2 * kbp) * 128 + lane * 4);
                uint4 a1 = *(const uint4*)(sEp + (mbG * 8 + 2 * kbp + 1) * 128 + lane * 4);
                #pragma unroll
                for (int nbl = 0; nbl < 8; nbl++) {
                    MMA8(acc[mb][nbl], a0, bb[nbl].x, bb[nbl].y);
                    MMA8(acc[mb][nbl], a1, bb[nbl].z, bb[nbl].w);
                }
            }
        }

        // ---- epilogue1: H = tf32(relu(D1 + A[i] + B[j] + C[i-j])), write permuted ----
        #pragma unroll
        for (int mb = 0; mb < 2; mb++) {
            #pragma unroll
            for (int nbl = 0; nbl < 8; nbl++) {
                const int colp = wn * 64 + nbl * 8 + 2 * tg;
                const float2 Av = *(const float2*)(sArow + colp);
                const int kb2 = wn * 8 + nbl;
                const int hbase = ((wm * 2 + mb) * 16 + kb2) * 128
                                + (g * 4 + ((2 * tg) & 3)) * 4 + 2 * (tg >> 1);
                #pragma unroll
                for (int h = 0; h < 2; h++) {
                    const int m = wm * 32 + mb * 16 + g + 8 * h;
                    const int j = j0 + m;
                    const float2 Bv = *(const float2*)(g_B + j * CP + colp);
                    const float2 Cv = *(const float2*)(g_C + (i - j + 511) * CP + colp);
                    float v0 = rtf32(fmaxf(acc[mb][nbl][2 * h]     + Av.x + Bv.x + Cv.x, 0.0f));
                    float v1 = rtf32(fmaxf(acc[mb][nbl][2 * h + 1] + Av.y + Bv.y + Cv.y, 0.0f));
                    sHp[hbase + h]     = v0;
                    sHp[hbase + h + 4] = v1;
                }
            }
        }
        __syncthreads();   // Hp complete; Ep dead

        // ---- GEMM2: D2 = H @ W2t (K=128) ----
        #pragma unroll
        for (int mb = 0; mb < 2; mb++)
            #pragma unroll
            for (int nbl = 0; nbl < 8; nbl++)
                #pragma unroll
                for (int u = 0; u < 4; u++) acc[mb][nbl][u] = 0.0f;

        #pragma unroll
        for (int kbp = 0; kbp < 8; kbp++) {
            uint4 bb[8];
            #pragma unroll
            for (int nbl = 0; nbl < 8; nbl++)
                bb[nbl] = *(const uint4*)(sW2p + (kbp * 16 + wn * 8 + nbl) * 128 + lane * 4);
            #pragma unroll
            for (int mb = 0; mb < 2; mb++) {
                const int mbG = wm * 2 + mb;
                uint4 a0 = *(const uint4*)(sHp + (mbG * 16 + 2 * kbp) * 128 + lane * 4);
                uint4 a1 = *(const uint4*)(sHp + (mbG * 16 + 2 * kbp + 1) * 128 + lane * 4);
                #pragma unroll
                for (int nbl = 0; nbl < 8; nbl++) {
                    MMA8(acc[mb][nbl], a0, bb[nbl].x, bb[nbl].y);
                    MMA8(acc[mb][nbl], a1, bb[nbl].z, bb[nbl].w);
                }
            }
        }

        // ---- epilogue2: out = D2 + b2, straight from registers ----
        #pragma unroll
        for (int mb = 0; mb < 2; mb++) {
            #pragma unroll
            for (int h = 0; h < 2; h++) {
                const int m = wm * 32 + mb * 16 + g + 8 * h;
                float* orow = out + ((size_t)(i * LSEQ + j0 + m)) * CP;
                #pragma unroll
                for (int nbl = 0; nbl < 8; nbl++) {
                    const int colp = wn * 64 + nbl * 8 + 2 * tg;
                    float2 o;
                    o.x = acc[mb][nbl][2 * h]     + b2r[nbl].x;
                    o.y = acc[mb][nbl][2 * h + 1] + b2r[nbl].y;
                    *(float2*)(orow + colp) = o;
                }
            }
        }
        // next phase0 writes Ep/sArow: both dead since mid-barrier; Hp/W2p
        // readers all passed; safe without extra barrier until next tile's
        // __syncthreads after E-build.
    }
}

// ======================= launch =======================
extern "C" void kernel_launch(void* const* d_in, const int* in_sizes, int n_in,
                              void* d_out, int out_size) {
    const float* s   = (const float*)d_in[0];
    const float* t   = (const float*)d_in[1];
    const float* sct = (const float*)d_in[2];
    const float* pre = (const float*)d_in[3];
    // d_in[4] = p_mask (all-ones, unused)
    const float* Wsp = (const float*)d_in[5];
    const float* bsp = (const float*)d_in[6];
    const float* Wrp = (const float*)d_in[7];
    const float* brp = (const float*)d_in[8];
    const float* W1  = (const float*)d_in[9];
    const float* b1  = (const float*)d_in[10];
    const float* W2  = (const float*)d_in[11];
    const float* b2  = (const float*)d_in[12];
    float* out = (float*)d_out;

    const int p_smem = (256 * 65 + 128 * 129 + 8 * 256 + 8 * 64) * 4;   // 142848
    cudaFuncSetAttribute(k_prep, cudaFuncAttributeMaxDynamicSharedMemorySize, p_smem);
    k_prep<<<80, 256, p_smem>>>(s, Wsp, bsp, Wrp, brp, W1, b1);

    cudaFuncSetAttribute(k_main, cudaFuncAttributeMaxDynamicSharedMemorySize, SMEM_TOTAL);
    k_main<<<152, 256, SMEM_TOTAL>>>(t, sct, pre, W1, W2, b2, out);
}

// round 15
// speedup vs baseline: 1.5661x; 1.5661x over previous
#include <cuda_runtime.h>
#include <cuda_fp16.h>
#include <cstdint>
#include <math.h>

#define LSEQ 512
#define CP   128

// ======================= device globals (no allocation) =======================
__device__ float g_A[LSEQ * CP];              // b1 + p_i[i] . W1[:,0:64]
__device__ float g_B[LSEQ * CP];              // p_i[j] . W1[:,64:128]
__device__ float g_C[1023 * CP];              // relpos path . W1[:,128:192]
__device__ uint32_t g_W1p[4096];              // W1s fp16 B-frags (2 superblocks x 16 nb x 128)
__device__ uint32_t g_W2p[8192];              // W2  fp16 B-frags (4 superblocks x 16 nb x 128)

__device__ __forceinline__ uint32_t packh2(float a, float b) {
    __half2 h = __floats2half2_rn(a, b);
    return *reinterpret_cast<uint32_t*>(&h);
}
__device__ __forceinline__ float2 unpackh2(uint32_t u) {
    __half2 h = *reinterpret_cast<__half2*>(&u);
    return __half22float2(h);
}

// m16n8k16 fp16 mma, f32 accum
#define MMA16(c, a, b0, b1)                                                     \
    asm volatile("mma.sync.aligned.m16n8k16.row.col.f32.f16.f16.f32 "           \
                 "{%0,%1,%2,%3}, {%4,%5,%6,%7}, {%8,%9}, {%0,%1,%2,%3};"        \
                 : "+f"((c)[0]), "+f"((c)[1]), "+f"((c)[2]), "+f"((c)[3])       \
                 : "r"((a).x), "r"((a).y), "r"((a).z), "r"((a).w),              \
                   "r"(b0), "r"(b1))

// ======================= merged prep kernel =======================
// blocks 0..63: A/B tables; 64..79: C table; 80: fp16 weight fragment packing
__global__ void k_prep(const float* __restrict__ s, const float* __restrict__ Wsp,
                       const float* __restrict__ bsp, const float* __restrict__ Wrp,
                       const float* __restrict__ brp, const float* __restrict__ W1,
                       const float* __restrict__ b1, const float* __restrict__ W2) {
    extern __shared__ float sm1[];
    const int tid = threadIdx.x;   // 256
    const int blk = blockIdx.x;
    if (blk < 64) {
        float* sWspT = sm1;                        // [d=256][f=64] pad 65
        float* sW1T  = sm1 + 256 * 65;             // [c=128][p=128] pad 129
        float* srow  = sW1T + 128 * 129;           // [8][256]
        float* prow  = srow + 8 * 256;             // [8][64]
        const int ii0 = blk * 8;

        #pragma unroll 8
        for (int x = tid; x < 64 * 256; x += 256) {
            int f = x >> 8, d = x & 255;
            sWspT[d * 65 + f] = Wsp[x];
        }
        #pragma unroll 8
        for (int x = tid; x < 128 * 128; x += 256) {
            int p = x >> 7, c = x & 127;
            sW1T[c * 129 + p] = W1[p * 256 + c];
        }
        #pragma unroll
        for (int x = tid; x < 8 * 256; x += 256)
            srow[x] = s[ii0 * 256 + x];
        __syncthreads();

        {
            const int f = tid & 63, il = tid >> 6;
            #pragma unroll
            for (int rep = 0; rep < 2; rep++) {
                const int i_loc = rep * 4 + il;
                float acc0 = bsp[f], acc1 = 0.0f;
                const float* sr = srow + i_loc * 256;
                #pragma unroll 8
                for (int d = 0; d < 256; d += 2) {
                    acc0 = fmaf(sr[d], sWspT[d * 65 + f], acc0);
                    acc1 = fmaf(sr[d + 1], sWspT[(d + 1) * 65 + f], acc1);
                }
                prow[i_loc * 64 + f] = acc0 + acc1;
            }
        }
        __syncthreads();
        {
            const int p = tid & 127, il = tid >> 7;
            #pragma unroll
            for (int rep = 0; rep < 4; rep++) {
                const int i_loc = rep * 2 + il;
                float a = b1[p], b = 0.0f;
                const float* pr = prow + i_loc * 64;
                #pragma unroll
                for (int fx = 0; fx < 64; fx++) {
                    float pv = pr[fx];
                    a = fmaf(pv, sW1T[fx * 129 + p], a);
                    b = fmaf(pv, sW1T[(64 + fx) * 129 + p], b);
                }
                g_A[(ii0 + i_loc) * CP + p] = a;
                g_B[(ii0 + i_loc) * CP + p] = b;
            }
        }
    } else if (blk < 80) {
        float* sWrpT  = sm1;                   // [g=64][f=64] pad 65
        float* sW1cT  = sm1 + 64 * 65;         // [g=64][p=128] pad 129
        float* semb   = sW1cT + 64 * 129;      // [4][64]
        float* srp    = semb + 4 * 64;         // [4][64]
        #pragma unroll 8
        for (int x = tid; x < 64 * 64; x += 256) {
            int f = x >> 6, g = x & 63;
            sWrpT[g * 65 + f] = Wrp[x];
        }
        #pragma unroll 8
        for (int x = tid; x < 128 * 64; x += 256) {
            int p = x >> 6, g = x & 63;
            sW1cT[g * 129 + p] = W1[p * 256 + 128 + g];
        }
        __syncthreads();
        const int d_base = (blk - 64) * 64;
        const int grp = tid >> 6, t2 = tid & 63;
        for (int it = 0; it < 16; it++) {
            const int d = d_base + it * 4 + grp;
            if (t2 < 32 && d < 1023) {
                const float L2 = 11.005624549193878f;   // log2(2056)
                float x = (float)(d - 511) * exp2f(-(float)t2 * (L2 / 32.0f));
                float sv, cv;
                sincospif(x, &sv, &cv);
                semb[grp * 64 + t2] = sv;
                semb[grp * 64 + 32 + t2] = cv;
            }
            __syncthreads();
            if (d < 1023) {
                float acc = brp[t2];
                const float* em = semb + grp * 64;
                #pragma unroll
                for (int g = 0; g < 64; g++) acc = fmaf(em[g], sWrpT[g * 65 + t2], acc);
                srp[grp * 64 + t2] = acc;
            }
            __syncthreads();
            {
                const int p = tid & 127;
                #pragma unroll
                for (int dd = 0; dd < 2; dd++) {
                    const int dl = (tid >> 7) + 2 * dd;
                    const int dg = d_base + it * 4 + dl;
                    if (dg < 1023) {
                        float acc = 0.0f;
                        const float* rpp = srp + dl * 64;
                        #pragma unroll
                        for (int g = 0; g < 64; g++) acc = fmaf(rpp[g], sW1cT[g * 129 + p], acc);
                        g_C[dg * CP + p] = acc;
                    }
                }
            }
            __syncthreads();
        }
    } else {
        // pack fp16 weights into B-fragment order in gmem.
        // B-frag for element (k,n): lane=(n&7)*4+((k&7)>>1), reg=(kb16&1)*2+((k&8)>>3)
        for (int x = tid; x < 4096; x += 256) {
            int n = x >> 5, kp = x & 31, k = 2 * kp;     // W1s: k<64, n<128
            float2 f = *(const float2*)(W1 + n * 256 + 192 + k);
            int kb = k >> 4;
            int idx = ((kb >> 1) * 16 + (n >> 3)) * 128
                    + ((n & 7) * 4 + ((k & 7) >> 1)) * 4
                    + (kb & 1) * 2 + ((k & 8) >> 3);
            g_W1p[idx] = packh2(f.x, f.y);
        }
        for (int x = tid; x < 8192; x += 256) {
            int q = x >> 6, kp = x & 63, p = 2 * kp;     // W2: k=p<128, n=q<128
            float2 f = *(const float2*)(W2 + q * 128 + p);
            int kb = p >> 4;
            int idx = ((kb >> 1) * 16 + (q >> 3)) * 128
                    + ((q & 7) * 4 + ((p & 7) >> 1)) * 4
                    + (kb & 1) * 2 + ((p & 8) >> 3);
            g_W2p[idx] = packh2(f.x, f.y);
        }
    }
}

// ======================= main kernel: fp16 m16n8k16, permuted operands =======================
// smem layout in u32 units:
#define U_W1P 0        // 4096 : W1 B-frags (kbp 0..1)x(nb 0..15)x128
#define U_W2P 4096     // 8192 : W2 B-frags (kbp 0..3)x(nb 0..15)x128
#define U_HP  12288    // 8192 : H A-frags  (mb 0..7)x(kb16 0..7)x128
#define U_EP  20480    // 4096 : E A-frags  (mb 0..7)x(kb16 0..3)x128   } overlaid
#define U_SS  20480    // 8448 : S table f16x2 [128][66]                } by sS
#define SMEM_TOTAL (28928 * 4)   // 115712 B -> 2 CTAs/SM

// E A-frag slot for element pair (m, c) with c even (numKb16 = 4)
__device__ __forceinline__ int eidx(int m, int c) {
    return ((m >> 4) * 4 + (c >> 4)) * 128
         + ((m & 7) * 4 + ((c >> 1) & 3)) * 4
         + ((m >> 3) & 1) + ((c & 8) >> 2);
}

__global__ __launch_bounds__(256, 2)
void k_main(const float* __restrict__ t, const float* __restrict__ sct,
            const float* __restrict__ pre, const float* __restrict__ b2v,
            float* __restrict__ out) {
    extern __shared__ uint32_t smu[];
    uint32_t* sW1p = smu + U_W1P;
    uint32_t* sW2p = smu + U_W2P;
    uint32_t* sHp  = smu + U_HP;
    uint32_t* sEp  = smu + U_EP;
    uint32_t* sS   = smu + U_SS;

    const int tid = threadIdx.x;
    const int wid = tid >> 5;
    const int lane = tid & 31;
    const int wm = wid >> 1;          // 0..3: rows [wm*32, +32)
    const int wn = wid & 1;           // 0..1: cols [wn*64, +64)
    const int g  = lane >> 2;
    const int tg = lane & 3;

    // ---- stage pre-packed weights once (straight uint4 copy) ----
    {
        const uint4* s1 = (const uint4*)g_W1p;
        const uint4* s2 = (const uint4*)g_W2p;
        uint4* d1 = (uint4*)sW1p;
        uint4* d2 = (uint4*)sW2p;
        #pragma unroll 4
        for (int x = tid; x < 1024; x += 256) d1[x] = s1[x];
        #pragma unroll 8
        for (int x = tid; x < 2048; x += 256) d2[x] = s2[x];
    }
    // per-thread b2 columns (constant across tiles)
    float2 b2r[8];
    #pragma unroll
    for (int nbl = 0; nbl < 8; nbl++)
        b2r[nbl] = *(const float2*)(b2v + wn * 64 + nbl * 8 + 2 * tg);
    __syncthreads();

    for (int tile = blockIdx.x; tile < 2048; tile += gridDim.x) {
        const int i = tile >> 2;
        const int j0 = (tile & 3) << 7;

        // ---- phase0: build E as fp16 A-frags ----
        {
            const int half = tid >> 7, m = tid & 127, j = j0 + m;
            const float* P = half ? sct : t;
            float dx = P[3 * i + 0] - P[3 * j + 0];
            float dy = P[3 * i + 1] - P[3 * j + 1];
            float dz = P[3 * i + 2] - P[3 * j + 2];
            float dist = sqrtf(dx * dx + dy * dy + dz * dz);
            const float inv_sig = 22.0f / 20.0f, step = 20.0f / 21.0f;
            float e[22];
            #pragma unroll
            for (int k = 0; k < 22; k++) {
                float r = (dist - k * step) * inv_sig;
                e[k] = __expf(-r * r);
            }
            #pragma unroll
            for (int c = 0; c < 11; c++)
                sEp[eidx(m, half * 22 + 2 * c)] = packh2(e[2 * c], e[2 * c + 1]);
            const float2* pp = (const float2*)(pre + ((size_t)(i * LSEQ + j)) * 20 + half * 10);
            #pragma unroll
            for (int c = 0; c < 5; c++) {
                float2 v = pp[c];
                sEp[eidx(m, 44 + half * 10 + 2 * c)] = packh2(v.x, v.y);
            }
        }
        __syncthreads();

        // ---- GEMM1: D1 = E @ W1s (K=64, fp16) ----
        float acc[2][8][4];
        #pragma unroll
        for (int mb = 0; mb < 2; mb++)
            #pragma unroll
            for (int nbl = 0; nbl < 8; nbl++)
                #pragma unroll
                for (int u = 0; u < 4; u++) acc[mb][nbl][u] = 0.0f;

        #pragma unroll
        for (int kbp = 0; kbp < 2; kbp++) {
            uint4 bb[8];
            #pragma unroll
            for (int nbl = 0; nbl < 8; nbl++)
                bb[nbl] = *(const uint4*)(sW1p + (kbp * 16 + wn * 8 + nbl) * 128 + lane * 4);
            #pragma unroll
            for (int mb = 0; mb < 2; mb++) {
                const int mbG = wm * 2 + mb;
                uint4 a0 = *(const uint4*)(sEp + (mbG * 4 + 2 * kbp) * 128 + lane * 4);
                uint4 a1 = *(const uint4*)(sEp + (mbG * 4 + 2 * kbp + 1) * 128 + lane * 4);
                #pragma unroll
                for (int nbl = 0; nbl < 8; nbl++) {
                    MMA16(acc[mb][nbl], a0, bb[nbl].x, bb[nbl].y);
                    MMA16(acc[mb][nbl], a1, bb[nbl].z, bb[nbl].w);
                }
            }
        }
        __syncthreads();   // E reads done; S-build may overwrite

        // ---- S-build: S[m] = A[i] + B[j0+m] + C[i-j0-m+511], f16x2, coalesced ----
        {
            const float4 A4 = *(const float4*)(g_A + i * CP + lane * 4);
            const int dbase = i - j0 + 511;
            #pragma unroll 4
            for (int r = 0; r < 16; r++) {
                const int m = wid * 16 + r;
                float4 B4 = *(const float4*)(g_B + (j0 + m) * CP + lane * 4);
                float4 C4 = *(const float4*)(g_C + (dbase - m) * CP + lane * 4);
                uint2 pck;
                pck.x = packh2(A4.x + B4.x + C4.x, A4.y + B4.y + C4.y);
                pck.y = packh2(A4.z + B4.z + C4.z, A4.w + B4.w + C4.w);
                *(uint2*)(sS + m * 66 + lane * 2) = pck;
            }
        }
        __syncthreads();

        // ---- epilogue1: H = f16(relu(D1 + S)) -> A-frag slots (numKb16=8) ----
        #pragma unroll
        for (int mb = 0; mb < 2; mb++) {
            const int m0r = wm * 32 + mb * 16 + g;
            #pragma unroll
            for (int nbl = 0; nbl < 8; nbl++) {
                const int colu = wn * 32 + nbl * 4 + tg;
                float2 s0 = unpackh2(sS[m0r * 66 + colu]);
                float2 s1 = unpackh2(sS[(m0r + 8) * 66 + colu]);
                uint2 hv;
                hv.x = packh2(fmaxf(acc[mb][nbl][0] + s0.x, 0.0f),
                              fmaxf(acc[mb][nbl][1] + s0.y, 0.0f));
                hv.y = packh2(fmaxf(acc[mb][nbl][2] + s1.x, 0.0f),
                              fmaxf(acc[mb][nbl][3] + s1.y, 0.0f));
                const int idx = ((wm * 2 + mb) * 8 + wn * 4 + (nbl >> 1)) * 128
                              + (g * 4 + tg) * 4 + 2 * (nbl & 1);
                *(uint2*)(sHp + idx) = hv;
            }
        }
        __syncthreads();

        // ---- GEMM2: D2 = H @ W2t (K=128, fp16) ----
        #pragma unroll
        for (int mb = 0; mb < 2; mb++)
            #pragma unroll
            for (int nbl = 0; nbl < 8; nbl++)
                #pragma unroll
                for (int u = 0; u < 4; u++) acc[mb][nbl][u] = 0.0f;

        #pragma unroll
        for (int kbp = 0; kbp < 4; kbp++) {
            uint4 bb[8];
            #pragma unroll
            for (int nbl = 0; nbl < 8; nbl++)
                bb[nbl] = *(const uint4*)(sW2p + (kbp * 16 + wn * 8 + nbl) * 128 + lane * 4);
            #pragma unroll
            for (int mb = 0; mb < 2; mb++) {
                const int mbG = wm * 2 + mb;
                uint4 a0 = *(const uint4*)(sHp + (mbG * 8 + 2 * kbp) * 128 + lane * 4);
                uint4 a1 = *(const uint4*)(sHp + (mbG * 8 + 2 * kbp + 1) * 128 + lane * 4);
                #pragma unroll
                for (int nbl = 0; nbl < 8; nbl++) {
                    MMA16(acc[mb][nbl], a0, bb[nbl].x, bb[nbl].y);
                    MMA16(acc[mb][nbl], a1, bb[nbl].z, bb[nbl].w);
                }
            }
        }

        // ---- epilogue2: out = D2 + b2, straight from registers ----
        #pragma unroll
        for (int mb = 0; mb < 2; mb++) {
            #pragma unroll
            for (int h = 0; h < 2; h++) {
                const int m = wm * 32 + mb * 16 + g + 8 * h;
                float* orow = out + ((size_t)(i * LSEQ + j0 + m)) * CP;
                #pragma unroll
                for (int nbl = 0; nbl < 8; nbl++) {
                    float2 o;
                    o.x = acc[mb][nbl][2 * h]     + b2r[nbl].x;
                    o.y = acc[mb][nbl][2 * h + 1] + b2r[nbl].y;
                    *(float2*)(orow + wn * 64 + nbl * 8 + 2 * tg) = o;
                }
            }
        }
        // next tile's E-build (sEp/sS region) does not overlap sHp/sW2p read in
        // GEMM2, and all sS readers passed the pre-GEMM2 barrier; safe.
    }
}

// ======================= launch =======================
extern "C" void kernel_launch(void* const* d_in, const int* in_sizes, int n_in,
                              void* d_out, int out_size) {
    const float* s   = (const float*)d_in[0];
    const float* t   = (const float*)d_in[1];
    const float* sct = (const float*)d_in[2];
    const float* pre = (const float*)d_in[3];
    // d_in[4] = p_mask (all-ones, unused)
    const float* Wsp = (const float*)d_in[5];
    const float* bsp = (const float*)d_in[6];
    const float* Wrp = (const float*)d_in[7];
    const float* brp = (const float*)d_in[8];
    const float* W1  = (const float*)d_in[9];
    const float* b1  = (const float*)d_in[10];
    const float* W2  = (const float*)d_in[11];
    const float* b2  = (const float*)d_in[12];
    float* out = (float*)d_out;

    const int p_smem = (256 * 65 + 128 * 129 + 8 * 256 + 8 * 64) * 4;   // 142848
    cudaFuncSetAttribute(k_prep, cudaFuncAttributeMaxDynamicSharedMemorySize, p_smem);
    k_prep<<<81, 256, p_smem>>>(s, Wsp, bsp, Wrp, brp, W1, b1, W2);

    cudaFuncSetAttribute(k_main, cudaFuncAttributeMaxDynamicSharedMemorySize, SMEM_TOTAL);
    k_main<<<304, 256, SMEM_TOTAL>>>(t, sct, pre, b2, out);
}

// round 17
// speedup vs baseline: 1.7857x; 1.1402x over previous
#include <cuda_runtime.h>
#include <cuda_fp16.h>
#include <cstdint>
#include <math.h>

#define LSEQ 512
#define CP   128

// ======================= device globals (no allocation) =======================
__device__ float g_A[LSEQ * CP];                       // b1 + p_i[i].W1[:,0:64]  (f32)
__device__ __align__(16) unsigned short g_Bh[512 * 128];   // p_i[j].W1[:,64:128]  (f16)
__device__ __align__(16) unsigned short g_Ch[1023 * 128];  // relpos.W1[:,128:192] (f16)
__device__ uint32_t g_W1p[4096];              // W1s fp16 B-frags
__device__ uint32_t g_W2p[8192];              // W2  fp16 B-frags

__device__ __forceinline__ uint32_t packh2(float a, float b) {
    __half2 h = __floats2half2_rn(a, b);
    return *reinterpret_cast<uint32_t*>(&h);
}
__device__ __forceinline__ float2 unpackh2(uint32_t u) {
    __half2 h = *reinterpret_cast<__half2*>(&u);
    return __half22float2(h);
}

// m16n8k16 fp16 mma, f32 accum
#define MMA16(c, a, b0, b1)                                                     \
    asm volatile("mma.sync.aligned.m16n8k16.row.col.f32.f16.f16.f32 "           \
                 "{%0,%1,%2,%3}, {%4,%5,%6,%7}, {%8,%9}, {%0,%1,%2,%3};"        \
                 : "+f"((c)[0]), "+f"((c)[1]), "+f"((c)[2]), "+f"((c)[3])       \
                 : "r"((a).x), "r"((a).y), "r"((a).z), "r"((a).w),              \
                   "r"(b0), "r"(b1))

// ======================= merged prep kernel =======================
// blocks 0..63: A/B tables (8 i each); 64..95: C table (32 d each); 96: weight packing
__global__ void k_prep(const float* __restrict__ s, const float* __restrict__ Wsp,
                       const float* __restrict__ bsp, const float* __restrict__ Wrp,
                       const float* __restrict__ brp, const float* __restrict__ W1,
                       const float* __restrict__ b1, const float* __restrict__ W2) {
    extern __shared__ float sm1[];
    const int tid = threadIdx.x;   // 256
    const int blk = blockIdx.x;
    if (blk < 64) {
        float* sWspT = sm1;                        // [d=256][f=64] pad 65
        float* sW1T  = sm1 + 256 * 65;             // [c=128][p=128] pad 129
        float* srow  = sW1T + 128 * 129;           // [8][256]
        float* prow  = srow + 8 * 256;             // [8][64]
        const int ii0 = blk * 8;

        #pragma unroll 4
        for (int x = tid; x < 64 * 64; x += 256) {     // f4-staged transpose of Wsp
            int f = x >> 6, d = (x & 63) * 4;
            float4 v = *(const float4*)(Wsp + f * 256 + d);
            sWspT[(d + 0) * 65 + f] = v.x;
            sWspT[(d + 1) * 65 + f] = v.y;
            sWspT[(d + 2) * 65 + f] = v.z;
            sWspT[(d + 3) * 65 + f] = v.w;
        }
        #pragma unroll 4
        for (int x = tid; x < 128 * 32; x += 256) {    // f4-staged transpose of W1[:, :128]
            int p = x >> 5, c = (x & 31) * 4;
            float4 v = *(const float4*)(W1 + p * 256 + c);
            sW1T[(c + 0) * 129 + p] = v.x;
            sW1T[(c + 1) * 129 + p] = v.y;
            sW1T[(c + 2) * 129 + p] = v.z;
            sW1T[(c + 3) * 129 + p] = v.w;
        }
        #pragma unroll
        for (int x = tid; x < 512; x += 256)
            ((float4*)srow)[x] = ((const float4*)(s + ii0 * 256))[x];
        __syncthreads();

        {
            const int f = tid & 63, il = tid >> 6;
            #pragma unroll
            for (int rep = 0; rep < 2; rep++) {
                const int i_loc = rep * 4 + il;
                float acc0 = bsp[f], acc1 = 0.0f;
                const float* sr = srow + i_loc * 256;
                #pragma unroll 8
                for (int d = 0; d < 256; d += 2) {
                    acc0 = fmaf(sr[d], sWspT[d * 65 + f], acc0);
                    acc1 = fmaf(sr[d + 1], sWspT[(d + 1) * 65 + f], acc1);
                }
                prow[i_loc * 64 + f] = acc0 + acc1;
            }
        }
        __syncthreads();
        {
            const int p = tid & 127, il = tid >> 7;
            #pragma unroll
            for (int rep = 0; rep < 4; rep++) {
                const int i_loc = rep * 2 + il;
                float a = b1[p], b = 0.0f;
                const float* pr = prow + i_loc * 64;
                #pragma unroll
                for (int fx = 0; fx < 64; fx++) {
                    float pv = pr[fx];
                    a = fmaf(pv, sW1T[fx * 129 + p], a);
                    b = fmaf(pv, sW1T[(64 + fx) * 129 + p], b);
                }
                g_A[(ii0 + i_loc) * CP + p] = a;
                g_Bh[(ii0 + i_loc) * CP + p] = __half_as_ushort(__float2half_rn(b));
            }
        }
    } else if (blk < 96) {
        float* sWrpT  = sm1;                   // [g=64][f=64] pad 65
        float* sW1cT  = sm1 + 64 * 65;         // [g=64][p=128] pad 129
        float* semb   = sW1cT + 64 * 129;      // [4][64]
        float* srp    = semb + 4 * 64;         // [4][64]
        #pragma unroll
        for (int x = tid; x < 64 * 16; x += 256) {     // f4-staged transpose of Wrp
            int f = x >> 4, g = (x & 15) * 4;
            float4 v = *(const float4*)(Wrp + f * 64 + g);
            sWrpT[(g + 0) * 65 + f] = v.x;
            sWrpT[(g + 1) * 65 + f] = v.y;
            sWrpT[(g + 2) * 65 + f] = v.z;
            sWrpT[(g + 3) * 65 + f] = v.w;
        }
        #pragma unroll 4
        for (int x = tid; x < 128 * 16; x += 256) {    // f4-staged transpose of W1[:,128:192]
            int p = x >> 4, g = (x & 15) * 4;
            float4 v = *(const float4*)(W1 + p * 256 + 128 + g);
            sW1cT[(g + 0) * 129 + p] = v.x;
            sW1cT[(g + 1) * 129 + p] = v.y;
            sW1cT[(g + 2) * 129 + p] = v.z;
            sW1cT[(g + 3) * 129 + p] = v.w;
        }
        __syncthreads();
        const int d_base = (blk - 64) * 32;
        const int grp = tid >> 6, t2 = tid & 63;
        for (int it = 0; it < 8; it++) {
            const int d = d_base + it * 4 + grp;
            if (t2 < 32 && d < 1023) {
                const float L2 = 11.005624549193878f;   // log2(2056)
                float x = (float)(d - 511) * exp2f(-(float)t2 * (L2 / 32.0f));
                float sv, cv;
                sincospif(x, &sv, &cv);
                semb[grp * 64 + t2] = sv;
                semb[grp * 64 + 32 + t2] = cv;
            }
            __syncthreads();
            if (d < 1023) {
                float acc = brp[t2];
                const float* em = semb + grp * 64;
                #pragma unroll
                for (int g = 0; g < 64; g++) acc = fmaf(em[g], sWrpT[g * 65 + t2], acc);
                srp[grp * 64 + t2] = acc;
            }
            __syncthreads();
            {
                const int p = tid & 127;
                #pragma unroll
                for (int dd = 0; dd < 2; dd++) {
                    const int dl = (tid >> 7) + 2 * dd;
                    const int dg = d_base + it * 4 + dl;
                    if (dg < 1023) {
                        float acc = 0.0f;
                        const float* rpp = srp + dl * 64;
                        #pragma unroll
                        for (int g = 0; g < 64; g++) acc = fmaf(rpp[g], sW1cT[g * 129 + p], acc);
                        g_Ch[dg * CP + p] = __half_as_ushort(__float2half_rn(acc));
                    }
                }
            }
            __syncthreads();
        }
    } else {
        // pack fp16 weights into B-fragment order in gmem.
        for (int x = tid; x < 4096; x += 256) {
            int n = x >> 5, kp = x & 31, k = 2 * kp;     // W1s: k<64, n<128
            float2 f = *(const float2*)(W1 + n * 256 + 192 + k);
            int kb = k >> 4;
            int idx = ((kb >> 1) * 16 + (n >> 3)) * 128
                    + ((n & 7) * 4 + ((k & 7) >> 1)) * 4
                    + (kb & 1) * 2 + ((k & 8) >> 3);
            g_W1p[idx] = packh2(f.x, f.y);
        }
        for (int x = tid; x < 8192; x += 256) {
            int q = x >> 6, kp = x & 63, p = 2 * kp;     // W2: k=p<128, n=q<128
            float2 f = *(const float2*)(W2 + q * 128 + p);
            int kb = p >> 4;
            int idx = ((kb >> 1) * 16 + (q >> 3)) * 128
                    + ((q & 7) * 4 + ((p & 7) >> 1)) * 4
                    + (kb & 1) * 2 + ((p & 8) >> 3);
            g_W2p[idx] = packh2(f.x, f.y);
        }
    }
}

// ======================= main kernel: fp16 m16n8k16, permuted operands =======================
#define U_W1P 0        // 4096 : W1 B-frags
#define U_W2P 4096     // 8192 : W2 B-frags
#define U_HP  12288    // 8192 : H A-frags
#define U_EP  20480    // 4096 : E A-frags   } overlaid
#define U_SS  20480    // 8448 : S f16x2 [128][66]
#define SMEM_TOTAL (28928 * 4)   // 115712 B -> 2 CTAs/SM

// E A-frag slot for element pair (m, c) with c even (numKb16 = 4)
__device__ __forceinline__ int eidx(int m, int c) {
    return ((m >> 4) * 4 + (c >> 4)) * 128
         + ((m & 7) * 4 + ((c >> 1) & 3)) * 4
         + ((m >> 3) & 1) + ((c & 8) >> 2);
}

__global__ __launch_bounds__(256, 2)
void k_main(const float* __restrict__ t, const float* __restrict__ sct,
            const float* __restrict__ pre, const float* __restrict__ b2v,
            float* __restrict__ out) {
    extern __shared__ uint32_t smu[];
    uint32_t* sW1p = smu + U_W1P;
    uint32_t* sW2p = smu + U_W2P;
    uint32_t* sHp  = smu + U_HP;
    uint32_t* sEp  = smu + U_EP;
    uint32_t* sS   = smu + U_SS;

    const int tid = threadIdx.x;
    const int wid = tid >> 5;
    const int lane = tid & 31;
    const int wm = wid >> 1;
    const int wn = wid & 1;
    const int g  = lane >> 2;
    const int tg = lane & 3;

    // ---- stage pre-packed weights once ----
    {
        const uint4* s1 = (const uint4*)g_W1p;
        const uint4* s2 = (const uint4*)g_W2p;
        uint4* d1 = (uint4*)sW1p;
        uint4* d2 = (uint4*)sW2p;
        #pragma unroll 4
        for (int x = tid; x < 1024; x += 256) d1[x] = s1[x];
        #pragma unroll 8
        for (int x = tid; x < 2048; x += 256) d2[x] = s2[x];
    }
    float2 b2r[8];
    #pragma unroll
    for (int nbl = 0; nbl < 8; nbl++)
        b2r[nbl] = *(const float2*)(b2v + wn * 64 + nbl * 8 + 2 * tg);
    __syncthreads();

    for (int tile = blockIdx.x; tile < 2048; tile += gridDim.x) {
        const int i = tile >> 2;
        const int j0 = (tile & 3) << 7;

        // ---- phase0: build E as fp16 A-frags (rotated store order -> fewer conflicts) ----
        {
            const int half = tid >> 7, m = tid & 127, j = j0 + m;
            const float* P = half ? sct : t;
            float dx = P[3 * i + 0] - P[3 * j + 0];
            float dy = P[3 * i + 1] - P[3 * j + 1];
            float dz = P[3 * i + 2] - P[3 * j + 2];
            float dist = sqrtf(dx * dx + dy * dy + dz * dz);
            const float inv_sig = 22.0f / 20.0f, step = 20.0f / 21.0f;
            const int r11 = (3 * m) % 11;
            #pragma unroll
            for (int c = 0; c < 11; c++) {
                int cc = c + r11;
                if (cc >= 11) cc -= 11;
                float r1 = (dist - (2 * cc) * step) * inv_sig;
                float r2 = (dist - (2 * cc + 1) * step) * inv_sig;
                sEp[eidx(m, half * 22 + 2 * cc)] = packh2(__expf(-r1 * r1), __expf(-r2 * r2));
            }
            const int r5 = m % 5;
            const float2* pp = (const float2*)(pre + ((size_t)(i * LSEQ + j)) * 20 + half * 10);
            #pragma unroll
            for (int c = 0; c < 5; c++) {
                int cc = c + r5;
                if (cc >= 5) cc -= 5;
                float2 v = pp[cc];
                sEp[eidx(m, 44 + half * 10 + 2 * cc)] = packh2(v.x, v.y);
            }
        }
        __syncthreads();

        // ---- GEMM1: D1 = E @ W1s (K=64, fp16) ----
        float acc[2][8][4];
        #pragma unroll
        for (int mb = 0; mb < 2; mb++)
            #pragma unroll
            for (int nbl = 0; nbl < 8; nbl++)
                #pragma unroll
                for (int u = 0; u < 4; u++) acc[mb][nbl][u] = 0.0f;

        #pragma unroll
        for (int kbp = 0; kbp < 2; kbp++) {
            uint4 bb[8];
            #pragma unroll
            for (int nbl = 0; nbl < 8; nbl++)
                bb[nbl] = *(const uint4*)(sW1p + (kbp * 16 + wn * 8 + nbl) * 128 + lane * 4);
            #pragma unroll
            for (int mb = 0; mb < 2; mb++) {
                const int mbG = wm * 2 + mb;
                uint4 a0 = *(const uint4*)(sEp + (mbG * 4 + 2 * kbp) * 128 + lane * 4);
                uint4 a1 = *(const uint4*)(sEp + (mbG * 4 + 2 * kbp + 1) * 128 + lane * 4);
                #pragma unroll
                for (int nbl = 0; nbl < 8; nbl++) {
                    MMA16(acc[mb][nbl], a0, bb[nbl].x, bb[nbl].y);
                    MMA16(acc[mb][nbl], a1, bb[nbl].z, bb[nbl].w);
                }
            }
        }
        __syncthreads();   // E reads done; S-build may overwrite

        // ---- S-build: S[m] = A[i](f32) + Bh[j0+m] + Ch[i-j0-m+511] (f16 tables) ----
        {
            const float4 A4 = *(const float4*)(g_A + i * CP + lane * 4);
            const int dbase = i - j0 + 511;
            #pragma unroll 4
            for (int r = 0; r < 16; r++) {
                const int m = wid * 16 + r;
                uint2 Bu = *(const uint2*)(g_Bh + (j0 + m) * CP + lane * 4);
                uint2 Cu = *(const uint2*)(g_Ch + (dbase - m) * CP + lane * 4);
                float2 b0 = unpackh2(Bu.x), b1 = unpackh2(Bu.y);
                float2 c0 = unpackh2(Cu.x), c1 = unpackh2(Cu.y);
                uint2 pck;
                pck.x = packh2(A4.x + b0.x + c0.x, A4.y + b0.y + c0.y);
                pck.y = packh2(A4.z + b1.x + c1.x, A4.w + b1.y + c1.y);
                *(uint2*)(sS + m * 66 + lane * 2) = pck;
            }
        }
        __syncthreads();

        // ---- epilogue1: H = f16(relu(D1 + S)) -> A-frag slots ----
        #pragma unroll
        for (int mb = 0; mb < 2; mb++) {
            const int m0r = wm * 32 + mb * 16 + g;
            #pragma unroll
            for (int nbl = 0; nbl < 8; nbl++) {
                const int colu = wn * 32 + nbl * 4 + tg;
                float2 s0 = unpackh2(sS[m0r * 66 + colu]);
                float2 s1 = unpackh2(sS[(m0r + 8) * 66 + colu]);
                uint2 hv;
                hv.x = packh2(fmaxf(acc[mb][nbl][0] + s0.x, 0.0f),
                              fmaxf(acc[mb][nbl][1] + s0.y, 0.0f));
                hv.y = packh2(fmaxf(acc[mb][nbl][2] + s1.x, 0.0f),
                              fmaxf(acc[mb][nbl][3] + s1.y, 0.0f));
                const int idx = ((wm * 2 + mb) * 8 + wn * 4 + (nbl >> 1)) * 128
                              + (g * 4 + tg) * 4 + 2 * (nbl & 1);
                *(uint2*)(sHp + idx) = hv;
            }
        }
        __syncthreads();

        // ---- GEMM2: D2 = H @ W2t (K=128, fp16) ----
        #pragma unroll
        for (int mb = 0; mb < 2; mb++)
            #pragma unroll
            for (int nbl = 0; nbl < 8; nbl++)
                #pragma unroll
                for (int u = 0; u < 4; u++) acc[mb][nbl][u] = 0.0f;

        #pragma unroll
        for (int kbp = 0; kbp < 4; kbp++) {
            uint4 bb[8];
            #pragma unroll
            for (int nbl = 0; nbl < 8; nbl++)
                bb[nbl] = *(const uint4*)(sW2p + (kbp * 16 + wn * 8 + nbl) * 128 + lane * 4);
            #pragma unroll
            for (int mb = 0; mb < 2; mb++) {
                const int mbG = wm * 2 + mb;
                uint4 a0 = *(const uint4*)(sHp + (mbG * 8 + 2 * kbp) * 128 + lane * 4);
                uint4 a1 = *(const uint4*)(sHp + (mbG * 8 + 2 * kbp + 1) * 128 + lane * 4);
                #pragma unroll
                for (int nbl = 0; nbl < 8; nbl++) {
                    MMA16(acc[mb][nbl], a0, bb[nbl].x, bb[nbl].y);
                    MMA16(acc[mb][nbl], a1, bb[nbl].z, bb[nbl].w);
                }
            }
        }

        // ---- epilogue2: out = D2 + b2, straight from registers ----
        #pragma unroll
        for (int mb = 0; mb < 2; mb++) {
            #pragma unroll
            for (int h = 0; h < 2; h++) {
                const int m = wm * 32 + mb * 16 + g + 8 * h;
                float* orow = out + ((size_t)(i * LSEQ + j0 + m)) * CP;
                #pragma unroll
                for (int nbl = 0; nbl < 8; nbl++) {
                    float2 o;
                    o.x = acc[mb][nbl][2 * h]     + b2r[nbl].x;
                    o.y = acc[mb][nbl][2 * h + 1] + b2r[nbl].y;
                    *(float2*)(orow + wn * 64 + nbl * 8 + 2 * tg) = o;
                }
            }
        }
    }
}

// ======================= launch =======================
extern "C" void kernel_launch(void* const* d_in, const int* in_sizes, int n_in,
                              void* d_out, int out_size) {
    const float* s   = (const float*)d_in[0];
    const float* t   = (const float*)d_in[1];
    const float* sct = (const float*)d_in[2];
    const float* pre = (const float*)d_in[3];
    // d_in[4] = p_mask (all-ones, unused)
    const float* Wsp = (const float*)d_in[5];
    const float* bsp = (const float*)d_in[6];
    const float* Wrp = (const float*)d_in[7];
    const float* brp = (const float*)d_in[8];
    const float* W1  = (const float*)d_in[9];
    const float* b1  = (const float*)d_in[10];
    const float* W2  = (const float*)d_in[11];
    const float* b2  = (const float*)d_in[12];
    float* out = (float*)d_out;

    const int p_smem = (256 * 65 + 128 * 129 + 8 * 256 + 8 * 64) * 4;   // 142848
    cudaFuncSetAttribute(k_prep, cudaFuncAttributeMaxDynamicSharedMemorySize, p_smem);
    k_prep<<<97, 256, p_smem>>>(s, Wsp, bsp, Wrp, brp, W1, b1, W2);

    cudaFuncSetAttribute(k_main, cudaFuncAttributeMaxDynamicSharedMemorySize, SMEM_TOTAL);
    k_main<<<304, 256, SMEM_TOTAL>>>(t, sct, pre, b2, out);
}